// round 1
// baseline (speedup 1.0000x reference)
#include <cuda_runtime.h>
#include <math.h>

#define NN 20000
#define EE 320000
#define GG 128

static inline int cdiv(int a, int b) { return (a + b - 1) / b; }

// ---------------- scratch (static device globals; no dynamic alloc) ----------------
__device__ float g_xl1[NN * 1024];
__device__ float g_xr1[NN * 1024];
__device__ float g_out1[NN * 1024];   // conv1 out, then bn1-normalized in place
__device__ float g_d256a[NN * 256];   // h256, later xl2
__device__ float g_xr2[NN * 256];
__device__ float g_out2[NN * 256];    // conv2 out, then bn2-normalized in place
__device__ float g_h64[NN * 64];
__device__ float g_score[EE * 4];
__device__ float g_smax[NN * 4];
__device__ float g_denom[NN * 4];
__device__ float g_bnsum[1024];
__device__ float g_bnsq[1024];
__device__ float g_scale[1024];
__device__ float g_shift[1024];
__device__ float g_pool[GG * 256];
__device__ float g_fc1o[GG * 64];

// ---------------- helpers ----------------
__device__ __forceinline__ void atomicMaxF(float* addr, float val) {
    int old = __float_as_int(*addr);
    while (__int_as_float(old) < val) {
        int assumed = old;
        old = atomicCAS((int*)addr, assumed, __float_as_int(val));
        if (old == assumed) break;
    }
}

// ---------------- SGEMM: C = A[M,K] @ W[K,N] (+bias, opt relu) ----------------
// BM=128 BN=64 BK=16, 256 threads, TM=8 TN=4
template <bool RELU, bool HAS_BIAS>
__global__ __launch_bounds__(256) void sgemm_kernel(
    const float* __restrict__ A, const float* __restrict__ W,
    const float* __restrict__ bias, float* __restrict__ C,
    int M, int N, int K)
{
    const int BM = 128, BN = 64, BK = 16, TM = 8, TN = 4;
    __shared__ float As[BK][BM + 1];
    __shared__ float Ws[BK][BN];
    int tid = threadIdx.x;
    int tx = tid & 15;       // n dir
    int ty = tid >> 4;       // m dir
    int rowBase = blockIdx.y * BM;
    int colBase = blockIdx.x * BN;

    float acc[TM][TN];
#pragma unroll
    for (int i = 0; i < TM; i++)
#pragma unroll
        for (int j = 0; j < TN; j++) acc[i][j] = 0.f;

    for (int k0 = 0; k0 < K; k0 += BK) {
        // A tile: BM x BK = 2048 elems
#pragma unroll
        for (int l = 0; l < 8; l++) {
            int idx = tid + l * 256;
            int r = idx >> 4;        // /BK
            int c = idx & 15;        // %BK
            int gr = rowBase + r;
            As[c][r] = (gr < M) ? A[(size_t)gr * K + k0 + c] : 0.f;
        }
        // W tile: BK x BN = 1024 elems
#pragma unroll
        for (int l = 0; l < 4; l++) {
            int idx = tid + l * 256;
            int r = idx >> 6;        // /BN
            int c = idx & 63;
            Ws[r][c] = W[(size_t)(k0 + r) * N + colBase + c];
        }
        __syncthreads();
#pragma unroll
        for (int k = 0; k < BK; k++) {
            float a[TM], b[TN];
#pragma unroll
            for (int i = 0; i < TM; i++) a[i] = As[k][ty * TM + i];
            float4 bv = *reinterpret_cast<const float4*>(&Ws[k][tx * TN]);
            b[0] = bv.x; b[1] = bv.y; b[2] = bv.z; b[3] = bv.w;
#pragma unroll
            for (int i = 0; i < TM; i++)
#pragma unroll
                for (int j = 0; j < TN; j++) acc[i][j] += a[i] * b[j];
        }
        __syncthreads();
    }
#pragma unroll
    for (int i = 0; i < TM; i++) {
        int r = rowBase + ty * TM + i;
        if (r >= M) continue;
#pragma unroll
        for (int j = 0; j < TN; j++) {
            int ccol = colBase + tx * TN + j;
            float v = acc[i][j];
            if (HAS_BIAS) v += bias[ccol];
            if (RELU) v = fmaxf(v, 0.f);
            C[(size_t)r * N + ccol] = v;
        }
    }
}

// ---------------- edge score (GATv2): score[e,h] + segment max ----------------
// one warp per edge; ee computed on the fly from smem we; att in smem.
template <int CT, int HSHIFT>
__global__ __launch_bounds__(256) void edge_score_kernel(
    const float* __restrict__ xl, const float* __restrict__ xr,
    const float* __restrict__ ea, const float* __restrict__ we,
    const float* __restrict__ att, const int* __restrict__ ei,
    float* __restrict__ score, float* __restrict__ smax)
{
    __shared__ float we_s[8 * CT];
    __shared__ float att_s[CT];
    int tid = threadIdx.x;
    for (int i = tid; i < 8 * CT; i += blockDim.x) we_s[i] = we[i];
    for (int i = tid; i < CT; i += blockDim.x) att_s[i] = att[i];
    __syncthreads();

    int lane = tid & 31;
    int wid = tid >> 5;
    int gw = blockIdx.x * 8 + wid;
    int totW = gridDim.x * 8;

    for (int e = gw; e < EE; e += totW) {
        int src = ei[e];
        int dst = ei[EE + e];
        float eav[8];
#pragma unroll
        for (int k = 0; k < 8; k++) eav[k] = ea[e * 8 + k];
        const float* xls = xl + (size_t)src * CT;
        const float* xrd = xr + (size_t)dst * CT;
        float acc[4] = {0.f, 0.f, 0.f, 0.f};
#pragma unroll
        for (int it = 0; it < CT / 32; it++) {
            int c = lane + 32 * it;
            const int h = (32 * it) >> HSHIFT;   // compile-time per it
            float eec = 0.f;
#pragma unroll
            for (int k = 0; k < 8; k++) eec += eav[k] * we_s[k * CT + c];
            float m = xls[c] + xrd[c] + eec;
            m = (m > 0.f) ? m : 0.2f * m;
            acc[h] += m * att_s[c];
        }
#pragma unroll
        for (int h = 0; h < 4; h++) {
#pragma unroll
            for (int off = 16; off > 0; off >>= 1)
                acc[h] += __shfl_xor_sync(0xffffffffu, acc[h], off);
        }
        if (lane == 0) {
#pragma unroll
            for (int h = 0; h < 4; h++) {
                score[e * 4 + h] = acc[h];
                atomicMaxF(&smax[dst * 4 + h], acc[h]);
            }
        }
    }
}

// ---------------- exp + denom ----------------
__global__ void edge_exp_kernel(const int* __restrict__ ei,
                                float* __restrict__ score,
                                const float* __restrict__ smax,
                                float* __restrict__ denom)
{
    int i = blockIdx.x * blockDim.x + threadIdx.x;
    if (i >= EE * 4) return;
    int e = i >> 2;
    int h = i & 3;
    int dst = ei[EE + e];
    float ex = expf(score[i] - smax[dst * 4 + h]);
    score[i] = ex;
    atomicAdd(&denom[dst * 4 + h], ex);
}

// ---------------- aggregate: out[dst] += alpha * xl[src] ----------------
template <int CT, int HSHIFT>
__global__ __launch_bounds__(256) void edge_agg_kernel(
    const float* __restrict__ xl, const int* __restrict__ ei,
    const float* __restrict__ score, const float* __restrict__ denom,
    float* __restrict__ out)
{
    int tid = threadIdx.x;
    int lane = tid & 31;
    int wid = tid >> 5;
    int gw = blockIdx.x * 8 + wid;
    int totW = gridDim.x * 8;

    for (int e = gw; e < EE; e += totW) {
        int src = ei[e];
        int dst = ei[EE + e];
        float a0 = score[e * 4 + 0] / denom[dst * 4 + 0];
        float a1 = score[e * 4 + 1] / denom[dst * 4 + 1];
        float a2 = score[e * 4 + 2] / denom[dst * 4 + 2];
        float a3 = score[e * 4 + 3] / denom[dst * 4 + 3];
        const float* xls = xl + (size_t)src * CT;
        float* od = out + (size_t)dst * CT;
#pragma unroll
        for (int it = 0; it < CT / 32; it++) {
            int c = lane + 32 * it;
            const int h = (32 * it) >> HSHIFT;
            float al = (h == 0) ? a0 : (h == 1) ? a1 : (h == 2) ? a2 : a3;
            atomicAdd(&od[c], al * xls[c]);
        }
    }
}

// ---------------- BN (fused bias + relu) ----------------
template <int C>
__global__ void bn_stats_kernel(const float* __restrict__ h,
                                const float* __restrict__ bias,
                                float* __restrict__ sum, float* __restrict__ sq)
{
    int c = blockIdx.y * blockDim.x + threadIdx.x;
    int r0 = blockIdx.x * 128;
    int r1 = min(NN, r0 + 128);
    float b = bias[c];
    float s = 0.f, q = 0.f;
    for (int r = r0; r < r1; r++) {
        float v = h[(size_t)r * C + c] + b;
        v = fmaxf(v, 0.f);
        s += v;
        q += v * v;
    }
    atomicAdd(&sum[c], s);
    atomicAdd(&sq[c], q);
}

__global__ void bn_final_kernel(const float* __restrict__ sum, const float* __restrict__ sq,
                                const float* __restrict__ g, const float* __restrict__ b,
                                float* __restrict__ scale, float* __restrict__ shift, int C)
{
    int c = blockIdx.x * blockDim.x + threadIdx.x;
    if (c >= C) return;
    const float invN = 1.f / (float)NN;
    float mu = sum[c] * invN;
    float var = sq[c] * invN - mu * mu;
    var = fmaxf(var, 0.f);
    float rs = rsqrtf(var + 1e-5f);
    float sc = g[c] * rs;
    scale[c] = sc;
    shift[c] = b[c] - mu * sc;
}

template <int C>
__global__ void bn_apply_kernel(float* __restrict__ h, const float* __restrict__ bias,
                                const float* __restrict__ scale, const float* __restrict__ shift)
{
    size_t i = (size_t)blockIdx.x * blockDim.x + threadIdx.x;
    size_t total = (size_t)NN * C;
    if (i >= total) return;
    int c = (int)(i % C);
    float v = fmaxf(h[i] + bias[c], 0.f);
    h[i] = v * scale[c] + shift[c];
}

// ---------------- pooling + head ----------------
__global__ void pool_kernel(const float* __restrict__ h, const int* __restrict__ batch,
                            float* __restrict__ pooled)
{
    size_t i = (size_t)blockIdx.x * blockDim.x + threadIdx.x;
    if (i >= (size_t)NN * 256) return;
    int node = (int)(i >> 8);
    int c = (int)(i & 255);
    atomicAdd(&pooled[batch[node] * 256 + c], h[i]);
}

__global__ void fc1_kernel(const float* __restrict__ pooled, const float* __restrict__ w,
                           const float* __restrict__ b, float* __restrict__ out)
{
    int gph = blockIdx.x;
    int j = threadIdx.x;
    float s = b[j];
    const float* p = pooled + gph * 256;
#pragma unroll 8
    for (int k = 0; k < 256; k++) s += p[k] * w[k * 64 + j];
    out[gph * 64 + j] = fmaxf(s, 0.f);
}

__global__ void fc2_kernel(const float* __restrict__ fc1o, const float* __restrict__ w,
                           const float* __restrict__ b, float* __restrict__ out)
{
    int gph = blockIdx.x * blockDim.x + threadIdx.x;
    if (gph >= GG) return;
    float s = b[0];
    const float* f = fc1o + gph * 64;
#pragma unroll
    for (int j = 0; j < 64; j++) s += f[j] * w[j];
    out[gph] = s;
}

__global__ void init_neg_kernel(float* __restrict__ p, int n)
{
    int i = blockIdx.x * blockDim.x + threadIdx.x;
    if (i < n) p[i] = -1e30f;
}

// ---------------- launch ----------------
extern "C" void kernel_launch(void* const* d_in, const int* in_sizes, int n_in,
                              void* d_out, int out_size)
{
    const float* x = (const float*)d_in[0];
    const float* edge_attr = (const float*)d_in[1];
    const int* edge_index;
    const int* batch;
    int wi;
    if (in_sizes[2] == 2 * EE) {  // setup_inputs dict order
        edge_index = (const int*)d_in[2];
        batch = (const int*)d_in[3];
        wi = 4;
    } else {                      // reference signature order (edge_index, batch last)
        edge_index = (const int*)d_in[n_in - 2];
        batch = (const int*)d_in[n_in - 1];
        wi = 2;
    }
    const float* dr1_w = (const float*)d_in[wi + 0];
    const float* dr1_b = (const float*)d_in[wi + 1];
    const float* dr2_w = (const float*)d_in[wi + 2];
    const float* dr2_b = (const float*)d_in[wi + 3];
    const float* c1_wl = (const float*)d_in[wi + 4];
    const float* c1_wr = (const float*)d_in[wi + 5];
    const float* c1_we = (const float*)d_in[wi + 6];
    const float* c1_att = (const float*)d_in[wi + 7];
    const float* c1_b = (const float*)d_in[wi + 8];
    const float* bn1_g = (const float*)d_in[wi + 9];
    const float* bn1_b = (const float*)d_in[wi + 10];
    const float* c2_wl = (const float*)d_in[wi + 11];
    const float* c2_wr = (const float*)d_in[wi + 12];
    const float* c2_we = (const float*)d_in[wi + 13];
    const float* c2_att = (const float*)d_in[wi + 14];
    const float* c2_b = (const float*)d_in[wi + 15];
    const float* bn2_g = (const float*)d_in[wi + 16];
    const float* bn2_b = (const float*)d_in[wi + 17];
    const float* fc1_w = (const float*)d_in[wi + 18];
    const float* fc1_b = (const float*)d_in[wi + 19];
    const float* fc2_w = (const float*)d_in[wi + 20];
    const float* fc2_b = (const float*)d_in[wi + 21];
    float* out = (float*)d_out;

    float *xl1, *xr1, *out1, *d256a, *xr2, *out2, *h64, *score, *smax, *denom;
    float *bnsum, *bnsq, *scalep, *shiftp, *pool, *fc1o;
    cudaGetSymbolAddress((void**)&xl1, g_xl1);
    cudaGetSymbolAddress((void**)&xr1, g_xr1);
    cudaGetSymbolAddress((void**)&out1, g_out1);
    cudaGetSymbolAddress((void**)&d256a, g_d256a);
    cudaGetSymbolAddress((void**)&xr2, g_xr2);
    cudaGetSymbolAddress((void**)&out2, g_out2);
    cudaGetSymbolAddress((void**)&h64, g_h64);
    cudaGetSymbolAddress((void**)&score, g_score);
    cudaGetSymbolAddress((void**)&smax, g_smax);
    cudaGetSymbolAddress((void**)&denom, g_denom);
    cudaGetSymbolAddress((void**)&bnsum, g_bnsum);
    cudaGetSymbolAddress((void**)&bnsq, g_bnsq);
    cudaGetSymbolAddress((void**)&scalep, g_scale);
    cudaGetSymbolAddress((void**)&shiftp, g_shift);
    cudaGetSymbolAddress((void**)&pool, g_pool);
    cudaGetSymbolAddress((void**)&fc1o, g_fc1o);

    dim3 blk256(256);

    // 1) h256 = relu(x @ dr1_w + b)   [20000,512]x[512,256]
    sgemm_kernel<true, true><<<dim3(cdiv(256, 64), cdiv(NN, 128)), blk256>>>(
        x, dr1_w, dr1_b, d256a, NN, 256, 512);
    // 2) h64 = h256 @ dr2_w + b
    sgemm_kernel<false, true><<<dim3(1, cdiv(NN, 128)), blk256>>>(
        d256a, dr2_w, dr2_b, h64, NN, 64, 256);
    // 3) xl1 / xr1
    sgemm_kernel<false, false><<<dim3(16, cdiv(NN, 128)), blk256>>>(
        h64, c1_wl, nullptr, xl1, NN, 1024, 64);
    sgemm_kernel<false, false><<<dim3(16, cdiv(NN, 128)), blk256>>>(
        h64, c1_wr, nullptr, xr1, NN, 1024, 64);

    // conv1 edge phase
    init_neg_kernel<<<cdiv(NN * 4, 256), blk256>>>(smax, NN * 4);
    cudaMemsetAsync(denom, 0, NN * 4 * sizeof(float), 0);
    cudaMemsetAsync(out1, 0, (size_t)NN * 1024 * sizeof(float), 0);
    edge_score_kernel<1024, 8><<<1280, blk256>>>(xl1, xr1, edge_attr, c1_we, c1_att,
                                                 edge_index, score, smax);
    edge_exp_kernel<<<cdiv(EE * 4, 256), blk256>>>(edge_index, score, smax, denom);
    edge_agg_kernel<1024, 8><<<1280, blk256>>>(xl1, edge_index, score, denom, out1);

    // bn1 (bias + relu fused)
    cudaMemsetAsync(bnsum, 0, 1024 * sizeof(float), 0);
    cudaMemsetAsync(bnsq, 0, 1024 * sizeof(float), 0);
    bn_stats_kernel<1024><<<dim3(cdiv(NN, 128), 4), blk256>>>(out1, c1_b, bnsum, bnsq);
    bn_final_kernel<<<4, blk256>>>(bnsum, bnsq, bn1_g, bn1_b, scalep, shiftp, 1024);
    bn_apply_kernel<1024><<<cdiv(NN * 1024, 256), blk256>>>(out1, c1_b, scalep, shiftp);

    // conv2 projections: xl2 (reuse d256a), xr2
    sgemm_kernel<false, false><<<dim3(4, cdiv(NN, 128)), blk256>>>(
        out1, c2_wl, nullptr, d256a, NN, 256, 1024);
    sgemm_kernel<false, false><<<dim3(4, cdiv(NN, 128)), blk256>>>(
        out1, c2_wr, nullptr, xr2, NN, 256, 1024);

    // conv2 edge phase
    init_neg_kernel<<<cdiv(NN * 4, 256), blk256>>>(smax, NN * 4);
    cudaMemsetAsync(denom, 0, NN * 4 * sizeof(float), 0);
    cudaMemsetAsync(out2, 0, (size_t)NN * 256 * sizeof(float), 0);
    edge_score_kernel<256, 6><<<1280, blk256>>>(d256a, xr2, edge_attr, c2_we, c2_att,
                                                edge_index, score, smax);
    edge_exp_kernel<<<cdiv(EE * 4, 256), blk256>>>(edge_index, score, smax, denom);
    edge_agg_kernel<256, 6><<<1280, blk256>>>(d256a, edge_index, score, denom, out2);

    // bn2
    cudaMemsetAsync(bnsum, 0, 256 * sizeof(float), 0);
    cudaMemsetAsync(bnsq, 0, 256 * sizeof(float), 0);
    bn_stats_kernel<256><<<dim3(cdiv(NN, 128), 1), blk256>>>(out2, c2_b, bnsum, bnsq);
    bn_final_kernel<<<1, blk256>>>(bnsum, bnsq, bn2_g, bn2_b, scalep, shiftp, 256);
    bn_apply_kernel<256><<<cdiv(NN * 256, 256), blk256>>>(out2, c2_b, scalep, shiftp);

    // pool + head
    cudaMemsetAsync(pool, 0, GG * 256 * sizeof(float), 0);
    pool_kernel<<<cdiv(NN * 256, 256), blk256>>>(out2, batch, pool);
    fc1_kernel<<<GG, 64>>>(pool, fc1_w, fc1_b, fc1o);
    fc2_kernel<<<1, 128>>>(fc1o, fc2_w, fc2_b, out);
    (void)out_size; (void)n_in; (void)in_sizes;
}

// round 2
// speedup vs baseline: 1.0048x; 1.0048x over previous
#include <cuda_runtime.h>
#include <math.h>

#define NN 20000
#define EE 320000
#define GG 128

static inline int cdiv(int a, int b) { return (a + b - 1) / b; }

// ---------------- scratch (static device globals; no dynamic alloc) ----------------
__device__ float g_xl1[NN * 1024];
__device__ float g_xr1[NN * 1024];
__device__ float g_out1[NN * 1024];   // conv1 out, then bn1-normalized in place
__device__ float g_d256a[NN * 256];   // h256, later xl2
__device__ float g_xr2[NN * 256];
__device__ float g_out2[NN * 256];    // conv2 out, then bn2-normalized in place
__device__ float g_h64[NN * 64];
__device__ float g_score[EE * 4];
__device__ float g_smax[NN * 4];
__device__ float g_denom[NN * 4];
__device__ float g_bnsum[1024];
__device__ float g_bnsq[1024];
__device__ float g_scale[1024];
__device__ float g_shift[1024];
__device__ float g_pool[GG * 256];
__device__ float g_fc1o[GG * 64];

// ---------------- helpers ----------------
__device__ __forceinline__ void atomicMaxF(float* addr, float val) {
    int old = __float_as_int(*addr);
    while (__int_as_float(old) < val) {
        int assumed = old;
        old = atomicCAS((int*)addr, assumed, __float_as_int(val));
        if (old == assumed) break;
    }
}

// ---------------- SGEMM: C = A[M,K] @ W[K,N] (+bias, opt relu) ----------------
// BM=128 BN=64 BK=16, 256 threads, TM=8 TN=4
template <bool RELU, bool HAS_BIAS>
__global__ __launch_bounds__(256) void sgemm_kernel(
    const float* __restrict__ A, const float* __restrict__ W,
    const float* __restrict__ bias, float* __restrict__ C,
    int M, int N, int K)
{
    const int BM = 128, BN = 64, BK = 16, TM = 8, TN = 4;
    __shared__ float As[BK][BM + 1];
    __shared__ float Ws[BK][BN];
    int tid = threadIdx.x;
    int tx = tid & 15;       // n dir
    int ty = tid >> 4;       // m dir
    int rowBase = blockIdx.y * BM;
    int colBase = blockIdx.x * BN;

    float acc[TM][TN];
#pragma unroll
    for (int i = 0; i < TM; i++)
#pragma unroll
        for (int j = 0; j < TN; j++) acc[i][j] = 0.f;

    for (int k0 = 0; k0 < K; k0 += BK) {
        // A tile: BM x BK = 2048 elems
#pragma unroll
        for (int l = 0; l < 8; l++) {
            int idx = tid + l * 256;
            int r = idx >> 4;        // /BK
            int c = idx & 15;        // %BK
            int gr = rowBase + r;
            As[c][r] = (gr < M) ? A[(size_t)gr * K + k0 + c] : 0.f;
        }
        // W tile: BK x BN = 1024 elems
#pragma unroll
        for (int l = 0; l < 4; l++) {
            int idx = tid + l * 256;
            int r = idx >> 6;        // /BN
            int c = idx & 63;
            Ws[r][c] = W[(size_t)(k0 + r) * N + colBase + c];
        }
        __syncthreads();
#pragma unroll
        for (int k = 0; k < BK; k++) {
            float a[TM], b[TN];
#pragma unroll
            for (int i = 0; i < TM; i++) a[i] = As[k][ty * TM + i];
            float4 bv = *reinterpret_cast<const float4*>(&Ws[k][tx * TN]);
            b[0] = bv.x; b[1] = bv.y; b[2] = bv.z; b[3] = bv.w;
#pragma unroll
            for (int i = 0; i < TM; i++)
#pragma unroll
                for (int j = 0; j < TN; j++) acc[i][j] += a[i] * b[j];
        }
        __syncthreads();
    }
#pragma unroll
    for (int i = 0; i < TM; i++) {
        int r = rowBase + ty * TM + i;
        if (r >= M) continue;
#pragma unroll
        for (int j = 0; j < TN; j++) {
            int ccol = colBase + tx * TN + j;
            float v = acc[i][j];
            if (HAS_BIAS) v += bias[ccol];
            if (RELU) v = fmaxf(v, 0.f);
            C[(size_t)r * N + ccol] = v;
        }
    }
}

// ---------------- edge score (GATv2): score[e,h] + segment max ----------------
// one warp per edge; ee computed on the fly from smem we; att in smem.
template <int CT, int HSHIFT>
__global__ __launch_bounds__(256) void edge_score_kernel(
    const float* __restrict__ xl, const float* __restrict__ xr,
    const float* __restrict__ ea, const float* __restrict__ we,
    const float* __restrict__ att, const int* __restrict__ ei,
    float* __restrict__ score, float* __restrict__ smax)
{
    __shared__ float we_s[8 * CT];
    __shared__ float att_s[CT];
    int tid = threadIdx.x;
    for (int i = tid; i < 8 * CT; i += blockDim.x) we_s[i] = we[i];
    for (int i = tid; i < CT; i += blockDim.x) att_s[i] = att[i];
    __syncthreads();

    int lane = tid & 31;
    int wid = tid >> 5;
    int gw = blockIdx.x * 8 + wid;
    int totW = gridDim.x * 8;

    for (int e = gw; e < EE; e += totW) {
        int src = ei[e];
        int dst = ei[EE + e];
        float eav[8];
#pragma unroll
        for (int k = 0; k < 8; k++) eav[k] = ea[e * 8 + k];
        const float* xls = xl + (size_t)src * CT;
        const float* xrd = xr + (size_t)dst * CT;
        float acc[4] = {0.f, 0.f, 0.f, 0.f};
#pragma unroll
        for (int it = 0; it < CT / 32; it++) {
            int c = lane + 32 * it;
            const int h = (32 * it) >> HSHIFT;   // compile-time per it
            float eec = 0.f;
#pragma unroll
            for (int k = 0; k < 8; k++) eec += eav[k] * we_s[k * CT + c];
            float m = xls[c] + xrd[c] + eec;
            m = (m > 0.f) ? m : 0.2f * m;
            acc[h] += m * att_s[c];
        }
#pragma unroll
        for (int h = 0; h < 4; h++) {
#pragma unroll
            for (int off = 16; off > 0; off >>= 1)
                acc[h] += __shfl_xor_sync(0xffffffffu, acc[h], off);
        }
        if (lane == 0) {
#pragma unroll
            for (int h = 0; h < 4; h++) {
                score[e * 4 + h] = acc[h];
                atomicMaxF(&smax[dst * 4 + h], acc[h]);
            }
        }
    }
}

// ---------------- exp + denom ----------------
__global__ void edge_exp_kernel(const int* __restrict__ ei,
                                float* __restrict__ score,
                                const float* __restrict__ smax,
                                float* __restrict__ denom)
{
    int i = blockIdx.x * blockDim.x + threadIdx.x;
    if (i >= EE * 4) return;
    int e = i >> 2;
    int h = i & 3;
    int dst = ei[EE + e];
    float ex = expf(score[i] - smax[dst * 4 + h]);
    score[i] = ex;
    atomicAdd(&denom[dst * 4 + h], ex);
}

// ---------------- aggregate: out[dst] += alpha * xl[src] ----------------
template <int CT, int HSHIFT>
__global__ __launch_bounds__(256) void edge_agg_kernel(
    const float* __restrict__ xl, const int* __restrict__ ei,
    const float* __restrict__ score, const float* __restrict__ denom,
    float* __restrict__ out)
{
    int tid = threadIdx.x;
    int lane = tid & 31;
    int wid = tid >> 5;
    int gw = blockIdx.x * 8 + wid;
    int totW = gridDim.x * 8;

    for (int e = gw; e < EE; e += totW) {
        int src = ei[e];
        int dst = ei[EE + e];
        float a0 = score[e * 4 + 0] / denom[dst * 4 + 0];
        float a1 = score[e * 4 + 1] / denom[dst * 4 + 1];
        float a2 = score[e * 4 + 2] / denom[dst * 4 + 2];
        float a3 = score[e * 4 + 3] / denom[dst * 4 + 3];
        const float* xls = xl + (size_t)src * CT;
        float* od = out + (size_t)dst * CT;
#pragma unroll
        for (int it = 0; it < CT / 32; it++) {
            int c = lane + 32 * it;
            const int h = (32 * it) >> HSHIFT;
            float al = (h == 0) ? a0 : (h == 1) ? a1 : (h == 2) ? a2 : a3;
            atomicAdd(&od[c], al * xls[c]);
        }
    }
}

// ---------------- BN (fused bias + relu) ----------------
template <int C>
__global__ void bn_stats_kernel(const float* __restrict__ h,
                                const float* __restrict__ bias,
                                float* __restrict__ sum, float* __restrict__ sq)
{
    int c = blockIdx.y * blockDim.x + threadIdx.x;
    int r0 = blockIdx.x * 128;
    int r1 = min(NN, r0 + 128);
    float b = bias[c];
    float s = 0.f, q = 0.f;
    for (int r = r0; r < r1; r++) {
        float v = h[(size_t)r * C + c] + b;
        v = fmaxf(v, 0.f);
        s += v;
        q += v * v;
    }
    atomicAdd(&sum[c], s);
    atomicAdd(&sq[c], q);
}

__global__ void bn_final_kernel(const float* __restrict__ sum, const float* __restrict__ sq,
                                const float* __restrict__ g, const float* __restrict__ b,
                                float* __restrict__ scale, float* __restrict__ shift, int C)
{
    int c = blockIdx.x * blockDim.x + threadIdx.x;
    if (c >= C) return;
    const float invN = 1.f / (float)NN;
    float mu = sum[c] * invN;
    float var = sq[c] * invN - mu * mu;
    var = fmaxf(var, 0.f);
    float rs = rsqrtf(var + 1e-5f);
    float sc = g[c] * rs;
    scale[c] = sc;
    shift[c] = b[c] - mu * sc;
}

template <int C>
__global__ void bn_apply_kernel(float* __restrict__ h, const float* __restrict__ bias,
                                const float* __restrict__ scale, const float* __restrict__ shift)
{
    size_t i = (size_t)blockIdx.x * blockDim.x + threadIdx.x;
    size_t total = (size_t)NN * C;
    if (i >= total) return;
    int c = (int)(i % C);
    float v = fmaxf(h[i] + bias[c], 0.f);
    h[i] = v * scale[c] + shift[c];
}

// ---------------- pooling + head ----------------
__global__ void pool_kernel(const float* __restrict__ h, const int* __restrict__ batch,
                            float* __restrict__ pooled)
{
    size_t i = (size_t)blockIdx.x * blockDim.x + threadIdx.x;
    if (i >= (size_t)NN * 256) return;
    int node = (int)(i >> 8);
    int c = (int)(i & 255);
    atomicAdd(&pooled[batch[node] * 256 + c], h[i]);
}

__global__ void fc1_kernel(const float* __restrict__ pooled, const float* __restrict__ w,
                           const float* __restrict__ b, float* __restrict__ out)
{
    int gph = blockIdx.x;
    int j = threadIdx.x;
    float s = b[j];
    const float* p = pooled + gph * 256;
#pragma unroll 8
    for (int k = 0; k < 256; k++) s += p[k] * w[k * 64 + j];
    out[gph * 64 + j] = fmaxf(s, 0.f);
}

__global__ void fc2_kernel(const float* __restrict__ fc1o, const float* __restrict__ w,
                           const float* __restrict__ b, float* __restrict__ out)
{
    int gph = blockIdx.x * blockDim.x + threadIdx.x;
    if (gph >= GG) return;
    float s = b[0];
    const float* f = fc1o + gph * 64;
#pragma unroll
    for (int j = 0; j < 64; j++) s += f[j] * w[j];
    out[gph] = s;
}

__global__ void init_neg_kernel(float* __restrict__ p, int n)
{
    int i = blockIdx.x * blockDim.x + threadIdx.x;
    if (i < n) p[i] = -1e30f;
}

// ---------------- launch ----------------
extern "C" void kernel_launch(void* const* d_in, const int* in_sizes, int n_in,
                              void* d_out, int out_size)
{
    const float* x = (const float*)d_in[0];
    const float* edge_attr = (const float*)d_in[1];
    const int* edge_index;
    const int* batch;
    int wi;
    if (in_sizes[2] == 2 * EE) {  // setup_inputs dict order
        edge_index = (const int*)d_in[2];
        batch = (const int*)d_in[3];
        wi = 4;
    } else {                      // reference signature order (edge_index, batch last)
        edge_index = (const int*)d_in[n_in - 2];
        batch = (const int*)d_in[n_in - 1];
        wi = 2;
    }
    const float* dr1_w = (const float*)d_in[wi + 0];
    const float* dr1_b = (const float*)d_in[wi + 1];
    const float* dr2_w = (const float*)d_in[wi + 2];
    const float* dr2_b = (const float*)d_in[wi + 3];
    const float* c1_wl = (const float*)d_in[wi + 4];
    const float* c1_wr = (const float*)d_in[wi + 5];
    const float* c1_we = (const float*)d_in[wi + 6];
    const float* c1_att = (const float*)d_in[wi + 7];
    const float* c1_b = (const float*)d_in[wi + 8];
    const float* bn1_g = (const float*)d_in[wi + 9];
    const float* bn1_b = (const float*)d_in[wi + 10];
    const float* c2_wl = (const float*)d_in[wi + 11];
    const float* c2_wr = (const float*)d_in[wi + 12];
    const float* c2_we = (const float*)d_in[wi + 13];
    const float* c2_att = (const float*)d_in[wi + 14];
    const float* c2_b = (const float*)d_in[wi + 15];
    const float* bn2_g = (const float*)d_in[wi + 16];
    const float* bn2_b = (const float*)d_in[wi + 17];
    const float* fc1_w = (const float*)d_in[wi + 18];
    const float* fc1_b = (const float*)d_in[wi + 19];
    const float* fc2_w = (const float*)d_in[wi + 20];
    const float* fc2_b = (const float*)d_in[wi + 21];
    float* out = (float*)d_out;

    float *xl1, *xr1, *out1, *d256a, *xr2, *out2, *h64, *score, *smax, *denom;
    float *bnsum, *bnsq, *scalep, *shiftp, *pool, *fc1o;
    cudaGetSymbolAddress((void**)&xl1, g_xl1);
    cudaGetSymbolAddress((void**)&xr1, g_xr1);
    cudaGetSymbolAddress((void**)&out1, g_out1);
    cudaGetSymbolAddress((void**)&d256a, g_d256a);
    cudaGetSymbolAddress((void**)&xr2, g_xr2);
    cudaGetSymbolAddress((void**)&out2, g_out2);
    cudaGetSymbolAddress((void**)&h64, g_h64);
    cudaGetSymbolAddress((void**)&score, g_score);
    cudaGetSymbolAddress((void**)&smax, g_smax);
    cudaGetSymbolAddress((void**)&denom, g_denom);
    cudaGetSymbolAddress((void**)&bnsum, g_bnsum);
    cudaGetSymbolAddress((void**)&bnsq, g_bnsq);
    cudaGetSymbolAddress((void**)&scalep, g_scale);
    cudaGetSymbolAddress((void**)&shiftp, g_shift);
    cudaGetSymbolAddress((void**)&pool, g_pool);
    cudaGetSymbolAddress((void**)&fc1o, g_fc1o);

    dim3 blk256(256);

    // 1) h256 = relu(x @ dr1_w + b)   [20000,512]x[512,256]
    sgemm_kernel<true, true><<<dim3(cdiv(256, 64), cdiv(NN, 128)), blk256>>>(
        x, dr1_w, dr1_b, d256a, NN, 256, 512);
    // 2) h64 = h256 @ dr2_w + b
    sgemm_kernel<false, true><<<dim3(1, cdiv(NN, 128)), blk256>>>(
        d256a, dr2_w, dr2_b, h64, NN, 64, 256);
    // 3) xl1 / xr1
    sgemm_kernel<false, false><<<dim3(16, cdiv(NN, 128)), blk256>>>(
        h64, c1_wl, nullptr, xl1, NN, 1024, 64);
    sgemm_kernel<false, false><<<dim3(16, cdiv(NN, 128)), blk256>>>(
        h64, c1_wr, nullptr, xr1, NN, 1024, 64);

    // conv1 edge phase
    init_neg_kernel<<<cdiv(NN * 4, 256), blk256>>>(smax, NN * 4);
    cudaMemsetAsync(denom, 0, NN * 4 * sizeof(float), 0);
    cudaMemsetAsync(out1, 0, (size_t)NN * 1024 * sizeof(float), 0);
    edge_score_kernel<1024, 8><<<1280, blk256>>>(xl1, xr1, edge_attr, c1_we, c1_att,
                                                 edge_index, score, smax);
    edge_exp_kernel<<<cdiv(EE * 4, 256), blk256>>>(edge_index, score, smax, denom);
    edge_agg_kernel<1024, 8><<<1280, blk256>>>(xl1, edge_index, score, denom, out1);

    // bn1 (bias + relu fused)
    cudaMemsetAsync(bnsum, 0, 1024 * sizeof(float), 0);
    cudaMemsetAsync(bnsq, 0, 1024 * sizeof(float), 0);
    bn_stats_kernel<1024><<<dim3(cdiv(NN, 128), 4), blk256>>>(out1, c1_b, bnsum, bnsq);
    bn_final_kernel<<<4, blk256>>>(bnsum, bnsq, bn1_g, bn1_b, scalep, shiftp, 1024);
    bn_apply_kernel<1024><<<cdiv(NN * 1024, 256), blk256>>>(out1, c1_b, scalep, shiftp);

    // conv2 projections: xl2 (reuse d256a), xr2
    sgemm_kernel<false, false><<<dim3(4, cdiv(NN, 128)), blk256>>>(
        out1, c2_wl, nullptr, d256a, NN, 256, 1024);
    sgemm_kernel<false, false><<<dim3(4, cdiv(NN, 128)), blk256>>>(
        out1, c2_wr, nullptr, xr2, NN, 256, 1024);

    // conv2 edge phase
    init_neg_kernel<<<cdiv(NN * 4, 256), blk256>>>(smax, NN * 4);
    cudaMemsetAsync(denom, 0, NN * 4 * sizeof(float), 0);
    cudaMemsetAsync(out2, 0, (size_t)NN * 256 * sizeof(float), 0);
    edge_score_kernel<256, 6><<<1280, blk256>>>(d256a, xr2, edge_attr, c2_we, c2_att,
                                                edge_index, score, smax);
    edge_exp_kernel<<<cdiv(EE * 4, 256), blk256>>>(edge_index, score, smax, denom);
    edge_agg_kernel<256, 6><<<1280, blk256>>>(d256a, edge_index, score, denom, out2);

    // bn2
    cudaMemsetAsync(bnsum, 0, 256 * sizeof(float), 0);
    cudaMemsetAsync(bnsq, 0, 256 * sizeof(float), 0);
    bn_stats_kernel<256><<<dim3(cdiv(NN, 128), 1), blk256>>>(out2, c2_b, bnsum, bnsq);
    bn_final_kernel<<<1, blk256>>>(bnsum, bnsq, bn2_g, bn2_b, scalep, shiftp, 256);
    bn_apply_kernel<256><<<cdiv(NN * 256, 256), blk256>>>(out2, c2_b, scalep, shiftp);

    // pool + head
    cudaMemsetAsync(pool, 0, GG * 256 * sizeof(float), 0);
    pool_kernel<<<cdiv(NN * 256, 256), blk256>>>(out2, batch, pool);
    fc1_kernel<<<GG, 64>>>(pool, fc1_w, fc1_b, fc1o);
    fc2_kernel<<<1, 128>>>(fc1o, fc2_w, fc2_b, out);
    (void)out_size; (void)n_in; (void)in_sizes;
}

// round 3
// speedup vs baseline: 2.5030x; 2.4910x over previous
#include <cuda_runtime.h>
#include <math.h>

#define NN 20000
#define EE 320000
#define GG 128

static inline int cdiv(int a, int b) { return (a + b - 1) / b; }

// ---------------- scratch ----------------
__device__ float g_xl1[NN * 1024];
__device__ float g_xr1[NN * 1024];
__device__ float g_out1[NN * 1024];
__device__ float g_d256a[NN * 256];
__device__ float g_xr2[NN * 256];
__device__ float g_out2[NN * 256];
__device__ float g_h64[NN * 64];
__device__ float g_score[EE * 4];       // fallback scores (CSR order)
__device__ int   g_deg[NN];
__device__ int   g_rowstart[NN + 1];
__device__ int   g_cursor[NN];
__device__ int   g_esrc[EE];
__device__ int   g_eid[EE];
__device__ float g_bnsum[1024];
__device__ float g_bnsq[1024];
__device__ float g_scale[1024];
__device__ float g_shift[1024];
__device__ float g_pool[GG * 256];
__device__ float g_fc1o[GG * 64];

// ---------------- CSR build ----------------
__global__ void hist_kernel(const int* __restrict__ ei, int* __restrict__ deg)
{
    int e = blockIdx.x * blockDim.x + threadIdx.x;
    if (e < EE) atomicAdd(&deg[ei[EE + e]], 1);
}

__global__ __launch_bounds__(512) void scan_kernel(const int* __restrict__ deg,
                                                   int* __restrict__ rowstart)
{
    __shared__ int ps[512];
    int t = threadIdx.x;
    const int CH = (NN + 511) / 512;   // 40
    int s0 = t * CH, s1 = min(NN, s0 + CH);
    int s = 0;
    for (int i = s0; i < s1; i++) s += deg[i];
    ps[t] = s;
    __syncthreads();
    for (int off = 1; off < 512; off <<= 1) {
        int v = (t >= off) ? ps[t - off] : 0;
        __syncthreads();
        ps[t] += v;
        __syncthreads();
    }
    int run = (t == 0) ? 0 : ps[t - 1];
    for (int i = s0; i < s1; i++) { rowstart[i] = run; run += deg[i]; }
    if (t == 511) rowstart[NN] = run;
}

__global__ void scatter_kernel(const int* __restrict__ ei, int* __restrict__ cursor,
                               int* __restrict__ esrc, int* __restrict__ eid)
{
    int e = blockIdx.x * blockDim.x + threadIdx.x;
    if (e >= EE) return;
    int dst = ei[EE + e];
    int pos = atomicAdd(&cursor[dst], 1);
    esrc[pos] = ei[e];
    eid[pos] = e;
}

// ---------------- SGEMM: C = A[M,K] @ W[K,N] (+bias, opt relu) ----------------
template <bool RELU, bool HAS_BIAS>
__global__ __launch_bounds__(256) void sgemm_kernel(
    const float* __restrict__ A, const float* __restrict__ W,
    const float* __restrict__ bias, float* __restrict__ C,
    int M, int N, int K)
{
    const int BM = 128, BN = 64, BK = 16, TM = 8, TN = 4;
    __shared__ float As[BK][BM + 1];
    __shared__ float Ws[BK][BN];
    int tid = threadIdx.x;
    int tx = tid & 15;
    int ty = tid >> 4;
    int rowBase = blockIdx.y * BM;
    int colBase = blockIdx.x * BN;

    float acc[TM][TN];
#pragma unroll
    for (int i = 0; i < TM; i++)
#pragma unroll
        for (int j = 0; j < TN; j++) acc[i][j] = 0.f;

    for (int k0 = 0; k0 < K; k0 += BK) {
#pragma unroll
        for (int l = 0; l < 8; l++) {
            int idx = tid + l * 256;
            int r = idx >> 4;
            int c = idx & 15;
            int gr = rowBase + r;
            As[c][r] = (gr < M) ? A[(size_t)gr * K + k0 + c] : 0.f;
        }
#pragma unroll
        for (int l = 0; l < 4; l++) {
            int idx = tid + l * 256;
            int r = idx >> 6;
            int c = idx & 63;
            Ws[r][c] = W[(size_t)(k0 + r) * N + colBase + c];
        }
        __syncthreads();
#pragma unroll
        for (int k = 0; k < BK; k++) {
            float a[TM], b[TN];
#pragma unroll
            for (int i = 0; i < TM; i++) a[i] = As[k][ty * TM + i];
            float4 bv = *reinterpret_cast<const float4*>(&Ws[k][tx * TN]);
            b[0] = bv.x; b[1] = bv.y; b[2] = bv.z; b[3] = bv.w;
#pragma unroll
            for (int i = 0; i < TM; i++)
#pragma unroll
                for (int j = 0; j < TN; j++) acc[i][j] += a[i] * b[j];
        }
        __syncthreads();
    }
#pragma unroll
    for (int i = 0; i < TM; i++) {
        int r = rowBase + ty * TM + i;
        if (r >= M) continue;
#pragma unroll
        for (int j = 0; j < TN; j++) {
            int ccol = colBase + tx * TN + j;
            float v = acc[i][j];
            if (HAS_BIAS) v += bias[ccol];
            if (RELU) v = fmaxf(v, 0.f);
            C[(size_t)r * N + ccol] = v;
        }
    }
}

// ---------------- fused GATv2 edge phase (per-dst CSR, no atomics) ----------------
// score -> softmax -> aggregate, one persistent block per stride of dst nodes.
template <int CT, int HSHIFT>
__global__ __launch_bounds__(256) void gat_edge_kernel(
    const float* __restrict__ xl, const float* __restrict__ xr,
    const float* __restrict__ ea, const float* __restrict__ we,
    const float* __restrict__ att,
    const int* __restrict__ rowstart, const int* __restrict__ esrc,
    const int* __restrict__ eid,
    float* __restrict__ gscore_fb,
    float* __restrict__ out)
{
    constexpr int MAXDEG = 256;
    constexpr int CU = CT / 256;
    __shared__ float we_s[8 * CT];
    __shared__ float att_s[CT];
    __shared__ float xr_s[CT];
    __shared__ float sc_s[MAXDEG * 4];
    int tid = threadIdx.x, lane = tid & 31, wid = tid >> 5;
    for (int i = tid; i < 8 * CT; i += 256) we_s[i] = we[i];
    for (int i = tid; i < CT; i += 256) att_s[i] = att[i];
    __syncthreads();

    for (int node = blockIdx.x; node < NN; node += gridDim.x) {
        int rs = rowstart[node];
        int deg = rowstart[node + 1] - rs;
        if (deg == 0) {
#pragma unroll
            for (int u = 0; u < CU; u++) out[(size_t)node * CT + u * 256 + tid] = 0.f;
            continue;
        }
#pragma unroll
        for (int u = 0; u < CU; u++)
            xr_s[u * 256 + tid] = xr[(size_t)node * CT + u * 256 + tid];
        __syncthreads();
        float* sc = (deg <= MAXDEG) ? sc_s : (gscore_fb + (size_t)rs * 4);

        // pass 1: raw scores, warp per edge
        for (int j = wid; j < deg; j += 8) {
            int src = esrc[rs + j];
            int e = eid[rs + j];
            float eav[8];
#pragma unroll
            for (int k = 0; k < 8; k++) eav[k] = __ldg(&ea[(size_t)e * 8 + k]);
            const float* xls = xl + (size_t)src * CT;
            float acc[4] = {0.f, 0.f, 0.f, 0.f};
#pragma unroll
            for (int it = 0; it < CT / 32; it++) {
                int c = lane + 32 * it;
                const int h = (32 * it) >> HSHIFT;
                float eec = 0.f;
#pragma unroll
                for (int k = 0; k < 8; k++) eec = fmaf(eav[k], we_s[k * CT + c], eec);
                float m = xls[c] + xr_s[c] + eec;
                m = (m > 0.f) ? m : 0.2f * m;
                acc[h] = fmaf(m, att_s[c], acc[h]);
            }
#pragma unroll
            for (int h = 0; h < 4; h++) {
#pragma unroll
                for (int off = 16; off > 0; off >>= 1)
                    acc[h] += __shfl_xor_sync(0xffffffffu, acc[h], off);
            }
            if (lane == 0) {
                sc[j * 4 + 0] = acc[0];
                sc[j * 4 + 1] = acc[1];
                sc[j * 4 + 2] = acc[2];
                sc[j * 4 + 3] = acc[3];
            }
        }
        __syncthreads();

        // softmax: warps 0..3, one head each
        if (wid < 4) {
            float mx = -1e30f;
            for (int j = lane; j < deg; j += 32) mx = fmaxf(mx, sc[j * 4 + wid]);
#pragma unroll
            for (int off = 16; off > 0; off >>= 1)
                mx = fmaxf(mx, __shfl_xor_sync(0xffffffffu, mx, off));
            float sum = 0.f;
            for (int j = lane; j < deg; j += 32) {
                float v = expf(sc[j * 4 + wid] - mx);
                sc[j * 4 + wid] = v;
                sum += v;
            }
#pragma unroll
            for (int off = 16; off > 0; off >>= 1)
                sum += __shfl_xor_sync(0xffffffffu, sum, off);
            float inv = 1.f / sum;
            for (int j = lane; j < deg; j += 32) sc[j * 4 + wid] *= inv;
        }
        __syncthreads();

        // pass 2: edge-sequential, channel-parallel, register accumulate
        float racc[CU];
#pragma unroll
        for (int u = 0; u < CU; u++) racc[u] = 0.f;
        for (int j = 0; j < deg; j++) {
            int src = esrc[rs + j];
            const float* xls = xl + (size_t)src * CT;
#pragma unroll
            for (int u = 0; u < CU; u++) {
                int c = u * 256 + tid;
                float al = sc[j * 4 + (c >> HSHIFT)];
                racc[u] = fmaf(al, xls[c], racc[u]);
            }
        }
#pragma unroll
        for (int u = 0; u < CU; u++)
            out[(size_t)node * CT + u * 256 + tid] = racc[u];
        __syncthreads();
    }
}

// ---------------- BN (fused bias + relu) ----------------
template <int C>
__global__ void bn_stats_kernel(const float* __restrict__ h,
                                const float* __restrict__ bias,
                                float* __restrict__ sum, float* __restrict__ sq)
{
    int c = blockIdx.y * blockDim.x + threadIdx.x;
    int r0 = blockIdx.x * 128;
    int r1 = min(NN, r0 + 128);
    float b = bias[c];
    float s = 0.f, q = 0.f;
    for (int r = r0; r < r1; r++) {
        float v = h[(size_t)r * C + c] + b;
        v = fmaxf(v, 0.f);
        s += v;
        q += v * v;
    }
    atomicAdd(&sum[c], s);
    atomicAdd(&sq[c], q);
}

__global__ void bn_final_kernel(const float* __restrict__ sum, const float* __restrict__ sq,
                                const float* __restrict__ g, const float* __restrict__ b,
                                float* __restrict__ scale, float* __restrict__ shift, int C)
{
    int c = blockIdx.x * blockDim.x + threadIdx.x;
    if (c >= C) return;
    const float invN = 1.f / (float)NN;
    float mu = sum[c] * invN;
    float var = sq[c] * invN - mu * mu;
    var = fmaxf(var, 0.f);
    float rs = rsqrtf(var + 1e-5f);
    float sc = g[c] * rs;
    scale[c] = sc;
    shift[c] = b[c] - mu * sc;
}

template <int C>
__global__ void bn_apply_kernel(float* __restrict__ h, const float* __restrict__ bias,
                                const float* __restrict__ scale, const float* __restrict__ shift)
{
    size_t i = (size_t)blockIdx.x * blockDim.x + threadIdx.x;
    size_t total = (size_t)NN * C;
    if (i >= total) return;
    int c = (int)(i % C);
    float v = fmaxf(h[i] + bias[c], 0.f);
    h[i] = v * scale[c] + shift[c];
}

// ---------------- pooling (batch is sorted: run-length accumulate) ------------
__global__ __launch_bounds__(256) void pool_kernel(const float* __restrict__ h,
                                                   const int* __restrict__ batch,
                                                   float* __restrict__ pooled)
{
    int c = threadIdx.x;
    int n0 = blockIdx.x * 128, n1 = min(NN, n0 + 128);
    if (n0 >= NN) return;
    float acc = 0.f;
    int cur = batch[n0];
    for (int n = n0; n < n1; n++) {
        int b = batch[n];
        if (b != cur) {
            atomicAdd(&pooled[cur * 256 + c], acc);
            acc = 0.f;
            cur = b;
        }
        acc += h[(size_t)n * 256 + c];
    }
    atomicAdd(&pooled[cur * 256 + c], acc);
}

__global__ void fc1_kernel(const float* __restrict__ pooled, const float* __restrict__ w,
                           const float* __restrict__ b, float* __restrict__ out)
{
    int gph = blockIdx.x;
    int j = threadIdx.x;
    float s = b[j];
    const float* p = pooled + gph * 256;
#pragma unroll 8
    for (int k = 0; k < 256; k++) s += p[k] * w[k * 64 + j];
    out[gph * 64 + j] = fmaxf(s, 0.f);
}

__global__ void fc2_kernel(const float* __restrict__ fc1o, const float* __restrict__ w,
                           const float* __restrict__ b, float* __restrict__ out)
{
    int gph = blockIdx.x * blockDim.x + threadIdx.x;
    if (gph >= GG) return;
    float s = b[0];
    const float* f = fc1o + gph * 64;
#pragma unroll
    for (int j = 0; j < 64; j++) s += f[j] * w[j];
    out[gph] = s;
}

// ---------------- launch ----------------
extern "C" void kernel_launch(void* const* d_in, const int* in_sizes, int n_in,
                              void* d_out, int out_size)
{
    const float* x = (const float*)d_in[0];
    const float* edge_attr = (const float*)d_in[1];
    const int* edge_index;
    const int* batch;
    int wi;
    if (in_sizes[2] == 2 * EE) {
        edge_index = (const int*)d_in[2];
        batch = (const int*)d_in[3];
        wi = 4;
    } else {
        edge_index = (const int*)d_in[n_in - 2];
        batch = (const int*)d_in[n_in - 1];
        wi = 2;
    }
    const float* dr1_w = (const float*)d_in[wi + 0];
    const float* dr1_b = (const float*)d_in[wi + 1];
    const float* dr2_w = (const float*)d_in[wi + 2];
    const float* dr2_b = (const float*)d_in[wi + 3];
    const float* c1_wl = (const float*)d_in[wi + 4];
    const float* c1_wr = (const float*)d_in[wi + 5];
    const float* c1_we = (const float*)d_in[wi + 6];
    const float* c1_att = (const float*)d_in[wi + 7];
    const float* c1_b = (const float*)d_in[wi + 8];
    const float* bn1_g = (const float*)d_in[wi + 9];
    const float* bn1_b = (const float*)d_in[wi + 10];
    const float* c2_wl = (const float*)d_in[wi + 11];
    const float* c2_wr = (const float*)d_in[wi + 12];
    const float* c2_we = (const float*)d_in[wi + 13];
    const float* c2_att = (const float*)d_in[wi + 14];
    const float* c2_b = (const float*)d_in[wi + 15];
    const float* bn2_g = (const float*)d_in[wi + 16];
    const float* bn2_b = (const float*)d_in[wi + 17];
    const float* fc1_w = (const float*)d_in[wi + 18];
    const float* fc1_b = (const float*)d_in[wi + 19];
    const float* fc2_w = (const float*)d_in[wi + 20];
    const float* fc2_b = (const float*)d_in[wi + 21];
    float* out = (float*)d_out;

    float *xl1, *xr1, *out1, *d256a, *xr2, *out2, *h64, *score;
    float *bnsum, *bnsq, *scalep, *shiftp, *pool, *fc1o;
    int *deg, *rowstart, *cursor, *esrc, *eid;
    cudaGetSymbolAddress((void**)&xl1, g_xl1);
    cudaGetSymbolAddress((void**)&xr1, g_xr1);
    cudaGetSymbolAddress((void**)&out1, g_out1);
    cudaGetSymbolAddress((void**)&d256a, g_d256a);
    cudaGetSymbolAddress((void**)&xr2, g_xr2);
    cudaGetSymbolAddress((void**)&out2, g_out2);
    cudaGetSymbolAddress((void**)&h64, g_h64);
    cudaGetSymbolAddress((void**)&score, g_score);
    cudaGetSymbolAddress((void**)&deg, g_deg);
    cudaGetSymbolAddress((void**)&rowstart, g_rowstart);
    cudaGetSymbolAddress((void**)&cursor, g_cursor);
    cudaGetSymbolAddress((void**)&esrc, g_esrc);
    cudaGetSymbolAddress((void**)&eid, g_eid);
    cudaGetSymbolAddress((void**)&bnsum, g_bnsum);
    cudaGetSymbolAddress((void**)&bnsq, g_bnsq);
    cudaGetSymbolAddress((void**)&scalep, g_scale);
    cudaGetSymbolAddress((void**)&shiftp, g_shift);
    cudaGetSymbolAddress((void**)&pool, g_pool);
    cudaGetSymbolAddress((void**)&fc1o, g_fc1o);

    dim3 blk256(256);

    // CSR build (dst-sorted)
    cudaMemsetAsync(deg, 0, NN * sizeof(int), 0);
    hist_kernel<<<cdiv(EE, 256), blk256>>>(edge_index, deg);
    scan_kernel<<<1, 512>>>(deg, rowstart);
    cudaMemcpyAsync(cursor, rowstart, NN * sizeof(int), cudaMemcpyDeviceToDevice, 0);
    scatter_kernel<<<cdiv(EE, 256), blk256>>>(edge_index, cursor, esrc, eid);

    // node MLP
    sgemm_kernel<true, true><<<dim3(4, cdiv(NN, 128)), blk256>>>(
        x, dr1_w, dr1_b, d256a, NN, 256, 512);
    sgemm_kernel<false, true><<<dim3(1, cdiv(NN, 128)), blk256>>>(
        d256a, dr2_w, dr2_b, h64, NN, 64, 256);
    sgemm_kernel<false, false><<<dim3(16, cdiv(NN, 128)), blk256>>>(
        h64, c1_wl, nullptr, xl1, NN, 1024, 64);
    sgemm_kernel<false, false><<<dim3(16, cdiv(NN, 128)), blk256>>>(
        h64, c1_wr, nullptr, xr1, NN, 1024, 64);

    // conv1 edge phase (fused)
    gat_edge_kernel<1024, 8><<<740, blk256>>>(xl1, xr1, edge_attr, c1_we, c1_att,
                                              rowstart, esrc, eid, score, out1);

    // bn1
    cudaMemsetAsync(bnsum, 0, 1024 * sizeof(float), 0);
    cudaMemsetAsync(bnsq, 0, 1024 * sizeof(float), 0);
    bn_stats_kernel<1024><<<dim3(cdiv(NN, 128), 4), blk256>>>(out1, c1_b, bnsum, bnsq);
    bn_final_kernel<<<4, blk256>>>(bnsum, bnsq, bn1_g, bn1_b, scalep, shiftp, 1024);
    bn_apply_kernel<1024><<<cdiv(NN * 1024, 256), blk256>>>(out1, c1_b, scalep, shiftp);

    // conv2 projections
    sgemm_kernel<false, false><<<dim3(4, cdiv(NN, 128)), blk256>>>(
        out1, c2_wl, nullptr, d256a, NN, 256, 1024);
    sgemm_kernel<false, false><<<dim3(4, cdiv(NN, 128)), blk256>>>(
        out1, c2_wr, nullptr, xr2, NN, 256, 1024);

    // conv2 edge phase (fused)
    gat_edge_kernel<256, 6><<<1184, blk256>>>(d256a, xr2, edge_attr, c2_we, c2_att,
                                              rowstart, esrc, eid, score, out2);

    // bn2
    cudaMemsetAsync(bnsum, 0, 256 * sizeof(float), 0);
    cudaMemsetAsync(bnsq, 0, 256 * sizeof(float), 0);
    bn_stats_kernel<256><<<dim3(cdiv(NN, 128), 1), blk256>>>(out2, c2_b, bnsum, bnsq);
    bn_final_kernel<<<1, blk256>>>(bnsum, bnsq, bn2_g, bn2_b, scalep, shiftp, 256);
    bn_apply_kernel<256><<<cdiv(NN * 256, 256), blk256>>>(out2, c2_b, scalep, shiftp);

    // pool + head
    cudaMemsetAsync(pool, 0, GG * 256 * sizeof(float), 0);
    pool_kernel<<<cdiv(NN, 128), blk256>>>(out2, batch, pool);
    fc1_kernel<<<GG, 64>>>(pool, fc1_w, fc1_b, fc1o);
    fc2_kernel<<<1, 128>>>(fc1o, fc2_w, fc2_b, out);
    (void)out_size; (void)n_in; (void)in_sizes;
}